// round 1
// baseline (speedup 1.0000x reference)
#include <cuda_runtime.h>
#include <math.h>

#define NN 20000
#define EE 640000

// ---------------- scratch (device globals; no allocation) ----------------
__device__ float g_fs[NN * 32];          // TP-input scalars after Linear1
__device__ float g_ss[NN * 32];          // self-connection scalars
__device__ float g_fv[NN * 96];          // TP-input vectors [N][32][3]
__device__ float g_sv[NN * 96];          // self-connection vectors
__device__ float g_w[(size_t)EE * 128];  // per-edge MLP weights [E][4*32]
__device__ float g_ns[NN * 64];          // scattered mid scalars
__device__ float g_nv[NN * 192];         // scattered mid vectors [N][64][3]
__device__ int   g_cnt[NN];
__device__ int   g_row[NN + 1];
__device__ int   g_cur[NN];
__device__ int   g_ord[EE];

__device__ __forceinline__ float gelu_f(float v) {
    // jax.nn.gelu(approximate=True): 0.5*x*(1+tanh(sqrt(2/pi)*(x+0.044715x^3)))
    float u = 0.7978845608028654f * (v + 0.044715f * v * v * v);
    return 0.5f * v * (1.0f + tanhf(u));
}

// ---------------- sort-by-dst machinery ----------------
__global__ void k_zero() {
    int i = blockIdx.x * blockDim.x + threadIdx.x;
    if (i < NN) g_cnt[i] = 0;
}

__global__ void k_hist(const int* __restrict__ dst) {
    int e = blockIdx.x * blockDim.x + threadIdx.x;
    if (e < EE) atomicAdd(&g_cnt[dst[e]], 1);
}

__global__ void k_scan() {
    __shared__ int part[1024];
    int t = threadIdx.x;
    const int CH = (NN + 1023) / 1024;  // 20
    int base = t * CH;
    int s = 0;
    for (int i = 0; i < CH; i++) {
        int idx = base + i;
        if (idx < NN) s += g_cnt[idx];
    }
    part[t] = s;
    __syncthreads();
    for (int off = 1; off < 1024; off <<= 1) {
        int v = 0;
        if (t >= off) v = part[t - off];
        __syncthreads();
        part[t] += v;
        __syncthreads();
    }
    int run = (t == 0) ? 0 : part[t - 1];
    for (int i = 0; i < CH; i++) {
        int idx = base + i;
        if (idx < NN) {
            g_row[idx] = run;
            g_cur[idx] = run;
            run += g_cnt[idx];
        }
    }
    if (t == 1023) g_row[NN] = part[1023];
}

__global__ void k_place(const int* __restrict__ dst) {
    int e = blockIdx.x * blockDim.x + threadIdx.x;
    if (e < EE) {
        int p = atomicAdd(&g_cur[dst[e]], 1);
        g_ord[p] = e;
    }
}

// ---------------- K1: first equivariant Linear ----------------
// warp per node, lane = output channel v
__global__ void k_lin1(const float* __restrict__ nsc, const float* __restrict__ nvec,
                       const float* __restrict__ W1sf, const float* __restrict__ W1ssw,
                       const float* __restrict__ W1vf, const float* __restrict__ W1vs) {
    __shared__ float wsf[1024], wss[1024], wvf[1024], wvs[1024];
    int t = threadIdx.x;
    for (int i = t; i < 1024; i += 256) {
        wsf[i] = W1sf[i];
        wss[i] = W1ssw[i];
        wvf[i] = W1vf[i];
        wvs[i] = W1vs[i];
    }
    __syncthreads();
    int warp = t >> 5, lane = t & 31;
    int n = blockIdx.x * 8 + warp;  // grid sized so n < NN always

    float s_l  = nsc[n * 32 + lane];
    int   b3l  = (n * 32 + lane) * 3;
    float vx_l = nvec[b3l + 0];
    float vy_l = nvec[b3l + 1];
    float vz_l = nvec[b3l + 2];

    float fs = 0.f, ss = 0.f;
    float fvx = 0.f, fvy = 0.f, fvz = 0.f;
    float svx = 0.f, svy = 0.f, svz = 0.f;
#pragma unroll
    for (int u = 0; u < 32; u++) {
        float s  = __shfl_sync(0xffffffffu, s_l, u);
        float vx = __shfl_sync(0xffffffffu, vx_l, u);
        float vy = __shfl_sync(0xffffffffu, vy_l, u);
        float vz = __shfl_sync(0xffffffffu, vz_l, u);
        float a = wsf[u * 32 + lane];
        float b = wss[u * 32 + lane];
        float c = wvf[u * 32 + lane];
        float d = wvs[u * 32 + lane];
        fs += s * a;
        ss += s * b;
        fvx += vx * c; fvy += vy * c; fvz += vz * c;
        svx += vx * d; svy += vy * d; svz += vz * d;
    }
    const float inv = 0.17677669529663687f;  // 1/sqrt(32)
    g_fs[n * 32 + lane] = fs * inv;
    g_ss[n * 32 + lane] = ss * inv;
    int b3 = (n * 32 + lane) * 3;
    g_fv[b3 + 0] = fvx * inv; g_fv[b3 + 1] = fvy * inv; g_fv[b3 + 2] = fvz * inv;
    g_sv[b3 + 0] = svx * inv; g_sv[b3 + 1] = svy * inv; g_sv[b3 + 2] = svz * inv;
}

// ---------------- K2a: radial MLP per edge ----------------
// thread per edge; activations in registers; weights broadcast from smem
__global__ void __launch_bounds__(256) k_mlp(const float* __restrict__ esa,
                                             const float* __restrict__ Wmlp0,
                                             const float* __restrict__ Wmlp1,
                                             const float* __restrict__ Wi0,
                                             const float* __restrict__ Wi1,
                                             const float* __restrict__ Wi2,
                                             const float* __restrict__ Wi3) {
    extern __shared__ float sm[];
    float* wm0T = sm;               // [64][16]  (transposed Wmlp0: column j contiguous)
    float* wm1  = sm + 1024;        // [64][64]  row-major [k][j]
    float* wi   = sm + 1024 + 4096; // [64][128] [k][m*32+u]
    int t = threadIdx.x;
    for (int i = t; i < 1024; i += 256) {
        int k = i & 15, j = i >> 4;
        wm0T[j * 16 + k] = Wmlp0[k * 64 + j];
    }
    for (int i = t; i < 4096; i += 256) wm1[i] = Wmlp1[i];
    for (int i = t; i < 2048; i += 256) {
        int k = i >> 5, u = i & 31;
        wi[k * 128 + u]      = Wi0[i];
        wi[k * 128 + 32 + u] = Wi1[i];
        wi[k * 128 + 64 + u] = Wi2[i];
        wi[k * 128 + 96 + u] = Wi3[i];
    }
    __syncthreads();

    int e = blockIdx.x * 256 + t;  // EE is an exact multiple of grid*256

    float x[16];
    {
        const float4* p = (const float4*)(esa + (size_t)e * 16);
        float4 a = p[0], b = p[1], c = p[2], d = p[3];
        x[0] = a.x; x[1] = a.y; x[2] = a.z; x[3] = a.w;
        x[4] = b.x; x[5] = b.y; x[6] = b.z; x[7] = b.w;
        x[8] = c.x; x[9] = c.y; x[10] = c.z; x[11] = c.w;
        x[12] = d.x; x[13] = d.y; x[14] = d.z; x[15] = d.w;
    }

    float h[64];
#pragma unroll
    for (int j = 0; j < 64; j++) h[j] = 0.f;

    // fused stage1+stage2: one h0 scalar at a time keeps registers low
    for (int k2 = 0; k2 < 64; k2++) {
        float t0 = 0.f;
        const float4* wc = (const float4*)(wm0T + k2 * 16);
#pragma unroll
        for (int kq = 0; kq < 4; kq++) {
            float4 w = wc[kq];
            t0 += x[kq * 4 + 0] * w.x + x[kq * 4 + 1] * w.y +
                  x[kq * 4 + 2] * w.z + x[kq * 4 + 3] * w.w;
        }
        t0 = gelu_f(t0 * 0.25f);  // /sqrt(16)
        const float4* wr = (const float4*)(wm1 + k2 * 64);
#pragma unroll
        for (int j4 = 0; j4 < 16; j4++) {
            float4 w = wr[j4];
            h[j4 * 4 + 0] += t0 * w.x;
            h[j4 * 4 + 1] += t0 * w.y;
            h[j4 * 4 + 2] += t0 * w.z;
            h[j4 * 4 + 3] += t0 * w.w;
        }
    }
#pragma unroll
    for (int j = 0; j < 64; j++) h[j] = gelu_f(h[j] * 0.125f);  // /sqrt(64)

    // stage3: 128 outputs in chunks of 8
    float* wout = g_w + (size_t)e * 128;
    for (int g = 0; g < 16; g++) {
        float acc0 = 0.f, acc1 = 0.f, acc2 = 0.f, acc3 = 0.f;
        float acc4 = 0.f, acc5 = 0.f, acc6 = 0.f, acc7 = 0.f;
        const float* wb = wi + g * 8;
#pragma unroll
        for (int k = 0; k < 64; k++) {
            float4 wa = *(const float4*)(wb + k * 128);
            float4 wb4 = *(const float4*)(wb + k * 128 + 4);
            float hk = h[k];
            acc0 += hk * wa.x; acc1 += hk * wa.y; acc2 += hk * wa.z; acc3 += hk * wa.w;
            acc4 += hk * wb4.x; acc5 += hk * wb4.y; acc6 += hk * wb4.z; acc7 += hk * wb4.w;
        }
        const float s8 = 0.125f;  // /sqrt(64)
        float4 o0 = make_float4(acc0 * s8, acc1 * s8, acc2 * s8, acc3 * s8);
        float4 o1 = make_float4(acc4 * s8, acc5 * s8, acc6 * s8, acc7 * s8);
        *(float4*)(wout + g * 8)     = o0;
        *(float4*)(wout + g * 8 + 4) = o1;
    }
}

// ---------------- K2b: gather + tensor product + segment reduce ----------------
// warp per node, lane = channel u
__global__ void k_gather(const float* __restrict__ eas, const float* __restrict__ eav,
                         const int* __restrict__ src) {
    int t = threadIdx.x;
    int n = (blockIdx.x * blockDim.x + t) >> 5;  // exactly NN warps
    int lane = t & 31;
    int beg = g_row[n], end = g_row[n + 1];

    float a0 = 0.f, a3 = 0.f;
    float a1x = 0.f, a1y = 0.f, a1z = 0.f;
    float a2x = 0.f, a2y = 0.f, a2z = 0.f;

    for (int base = beg; base < end; base += 32) {
        int cnt = min(32, end - base);
        int idx = 0, s = 0;
        float vx = 0.f, vy = 0.f, vz = 0.f, ea = 0.f;
        if (lane < cnt) {
            idx = g_ord[base + lane];
            s = src[idx];
            vx = eav[idx * 3 + 0];
            vy = eav[idx * 3 + 1];
            vz = eav[idx * 3 + 2];
            ea = eas[idx];
        }
        for (int i = 0; i < cnt; i++) {
            int ide = __shfl_sync(0xffffffffu, idx, i);
            int se  = __shfl_sync(0xffffffffu, s, i);
            float evx = __shfl_sync(0xffffffffu, vx, i);
            float evy = __shfl_sync(0xffffffffu, vy, i);
            float evz = __shfl_sync(0xffffffffu, vz, i);
            float eae = __shfl_sync(0xffffffffu, ea, i);

            const float* wp = g_w + (size_t)ide * 128;
            float w0 = wp[lane];
            float w1 = wp[32 + lane];
            float w2 = wp[64 + lane];
            float w3 = wp[96 + lane];
            float es = g_fs[se * 32 + lane];
            int b3 = (se * 32 + lane) * 3;
            float fx = g_fv[b3 + 0];
            float fy = g_fv[b3 + 1];
            float fz = g_fv[b3 + 2];

            float dot = fx * evx + fy * evy + fz * evz;
            a0 += w0 * es * eae;
            a3 += w3 * dot;
            float w1es = w1 * es;
            a1x += w1es * evx; a1y += w1es * evy; a1z += w1es * evz;
            float w2ea = w2 * eae;
            a2x += w2ea * fx; a2y += w2ea * fy; a2z += w2ea * fz;
        }
    }

    const float inv_nb = 0.17677669529663687f;  // 1/sqrt(32)
    const float inv_s3 = 0.5773502691896258f;   // 1/sqrt(3)
    g_ns[n * 64 + lane]      = a0 * inv_nb;
    g_ns[n * 64 + 32 + lane] = a3 * inv_s3 * inv_nb;
    int ba = n * 192 + lane * 3;
    g_nv[ba + 0] = a1x * inv_nb; g_nv[ba + 1] = a1y * inv_nb; g_nv[ba + 2] = a1z * inv_nb;
    int bb = n * 192 + (32 + lane) * 3;
    g_nv[bb + 0] = a2x * inv_nb; g_nv[bb + 1] = a2y * inv_nb; g_nv[bb + 2] = a2z * inv_nb;
}

// ---------------- K3: second Linear + self-connection mix ----------------
__global__ void k_lin2(const float* __restrict__ W2s, const float* __restrict__ W2v,
                       float* __restrict__ out) {
    __shared__ float w2s[2048], w2v[2048];
    int t = threadIdx.x;
    for (int i = t; i < 2048; i += 256) {
        w2s[i] = W2s[i];
        w2v[i] = W2v[i];
    }
    __syncthreads();
    int warp = t >> 5, lane = t & 31;
    int n = blockIdx.x * 8 + warp;

    float nsa = g_ns[n * 64 + lane];
    float nsb = g_ns[n * 64 + 32 + lane];
    int ba = n * 192 + lane * 3;
    int bb = n * 192 + (32 + lane) * 3;
    float vax = g_nv[ba + 0], vay = g_nv[ba + 1], vaz = g_nv[ba + 2];
    float vbx = g_nv[bb + 0], vby = g_nv[bb + 1], vbz = g_nv[bb + 2];

    float cs = 0.f, cvx = 0.f, cvy = 0.f, cvz = 0.f;
#pragma unroll
    for (int j = 0; j < 32; j++) {
        float sj = __shfl_sync(0xffffffffu, nsa, j);
        float xj = __shfl_sync(0xffffffffu, vax, j);
        float yj = __shfl_sync(0xffffffffu, vay, j);
        float zj = __shfl_sync(0xffffffffu, vaz, j);
        float ws = w2s[j * 32 + lane];
        float wv = w2v[j * 32 + lane];
        cs += sj * ws;
        cvx += xj * wv; cvy += yj * wv; cvz += zj * wv;
    }
#pragma unroll
    for (int j = 0; j < 32; j++) {
        float sj = __shfl_sync(0xffffffffu, nsb, j);
        float xj = __shfl_sync(0xffffffffu, vbx, j);
        float yj = __shfl_sync(0xffffffffu, vby, j);
        float zj = __shfl_sync(0xffffffffu, vbz, j);
        float ws = w2s[(32 + j) * 32 + lane];
        float wv = w2v[(32 + j) * 32 + lane];
        cs += sj * ws;
        cvx += xj * wv; cvy += yj * wv; cvz += zj * wv;
    }
    const float inv_mid = 0.125f;                 // 1/sqrt(64)
    const float cc = 0.9238795325112867f;         // cos(pi/8)
    const float sc = 0.3826834323650898f;         // sin(pi/8)
    float ssv = g_ss[n * 32 + lane];
    out[n * 32 + lane] = cc * ssv + sc * cs * inv_mid;

    int b3 = (n * 32 + lane) * 3;
    float* ov = out + NN * 32;
    ov[b3 + 0] = cc * g_sv[b3 + 0] + sc * cvx * inv_mid;
    ov[b3 + 1] = cc * g_sv[b3 + 1] + sc * cvy * inv_mid;
    ov[b3 + 2] = cc * g_sv[b3 + 2] + sc * cvz * inv_mid;
}

// ---------------- launch ----------------
extern "C" void kernel_launch(void* const* d_in, const int* in_sizes, int n_in,
                              void* d_out, int out_size) {
    const float* node_scalars = (const float*)d_in[0];
    const float* node_vectors = (const float*)d_in[1];
    const float* edge_attr_s  = (const float*)d_in[2];
    const float* edge_attr_v  = (const float*)d_in[3];
    const float* edge_scalar  = (const float*)d_in[4];
    const int*   edge_src     = (const int*)d_in[5];
    const int*   edge_dst     = (const int*)d_in[6];
    const float* W1s_feat     = (const float*)d_in[7];
    const float* W1s_self     = (const float*)d_in[8];
    const float* W1v_feat     = (const float*)d_in[9];
    const float* W1v_self     = (const float*)d_in[10];
    const float* Wmlp0        = (const float*)d_in[11];
    const float* Wmlp1        = (const float*)d_in[12];
    const float* Wi0          = (const float*)d_in[13];
    const float* Wi1          = (const float*)d_in[14];
    const float* Wi2          = (const float*)d_in[15];
    const float* Wi3          = (const float*)d_in[16];
    const float* W2s          = (const float*)d_in[17];
    const float* W2v          = (const float*)d_in[18];
    float* out = (float*)d_out;

    static bool attr_set = false;
    if (!attr_set) {
        cudaFuncSetAttribute(k_mlp, cudaFuncAttributeMaxDynamicSharedMemorySize, 13312 * 4);
        attr_set = true;
    }

    // sort edges by destination
    k_zero<<<(NN + 255) / 256, 256>>>();
    k_hist<<<EE / 256, 256>>>(edge_dst);
    k_scan<<<1, 1024>>>();
    k_place<<<EE / 256, 256>>>(edge_dst);

    // node linear 1
    k_lin1<<<NN / 8, 256>>>(node_scalars, node_vectors, W1s_feat, W1s_self, W1v_feat, W1v_self);

    // per-edge radial MLP
    k_mlp<<<EE / 256, 256, 13312 * 4>>>(edge_scalar, Wmlp0, Wmlp1, Wi0, Wi1, Wi2, Wi3);

    // gather + tensor product + segment sum
    k_gather<<<(NN * 32) / 256, 256>>>(edge_attr_s, edge_attr_v, edge_src);

    // node linear 2 + mix
    k_lin2<<<NN / 8, 256>>>(W2s, W2v, out);
}

// round 2
// speedup vs baseline: 1.0772x; 1.0772x over previous
#include <cuda_runtime.h>
#include <math.h>

#define NN 20000
#define EE 640000

// ---------------- scratch (device globals; no allocation) ----------------
__device__ float g_fs[NN * 32];          // TP-input scalars after Linear1
__device__ float g_ss[NN * 32];          // self-connection scalars
__device__ float g_fv[NN * 96];          // TP-input vectors [N][32][3]
__device__ float g_sv[NN * 96];          // self-connection vectors
__device__ float g_w[(size_t)EE * 128];  // per-edge MLP weights [E][4*32]
__device__ float g_ns[NN * 64];          // scattered mid scalars
__device__ float g_nv[NN * 192];         // scattered mid vectors [N][64][3]
__device__ int   g_cnt[NN];
__device__ int   g_row[NN + 1];
__device__ int   g_cur[NN];
__device__ int   g_ord[EE];

// ---------------- packed f32x2 helpers (Blackwell FFMA2 path) ----------------
typedef unsigned long long ull;

__device__ __forceinline__ ull pk2(float a, float b) {
    ull r; asm("mov.b64 %0,{%1,%2};" : "=l"(r) : "f"(a), "f"(b)); return r;
}
__device__ __forceinline__ void upk2(ull v, float& a, float& b) {
    asm("mov.b64 {%0,%1},%2;" : "=f"(a), "=f"(b) : "l"(v));
}
__device__ __forceinline__ ull fma2(ull a, ull b, ull c) {
    ull r; asm("fma.rn.f32x2 %0,%1,%2,%3;" : "=l"(r) : "l"(a), "l"(b), "l"(c)); return r;
}
__device__ __forceinline__ ull mul2(ull a, ull b) {
    ull r; asm("mul.rn.f32x2 %0,%1,%2;" : "=l"(r) : "l"(a), "l"(b)); return r;
}
__device__ __forceinline__ ull add2(ull a, ull b) {
    ull r; asm("add.rn.f32x2 %0,%1,%2;" : "=l"(r) : "l"(a), "l"(b)); return r;
}
__device__ __forceinline__ float tanh_ap(float x) {
    float r; asm("tanh.approx.f32 %0,%1;" : "=f"(r) : "f"(x)); return r;
}

// gelu(tanh approx) on a packed pair: 0.5*v*(1+tanh(v*(c0 + c1*v^2)))
__device__ __forceinline__ ull gelu2(ull v) {
    const ull C0 = pk2(0.7978845608028654f, 0.7978845608028654f);
    const ull C1 = pk2(0.03567740814183418f, 0.03567740814183418f); // 0.79788456*0.044715
    const ull H2 = pk2(0.5f, 0.5f);
    const ull O2 = pk2(1.0f, 1.0f);
    ull vv = mul2(v, v);
    ull u  = mul2(fma2(vv, C1, C0), v);
    float ulo, uhi; upk2(u, ulo, uhi);
    ull t = pk2(tanh_ap(ulo), tanh_ap(uhi));
    return mul2(mul2(v, H2), add2(O2, t));
}

__device__ __forceinline__ float gelu_f(float v) {
    float u = 0.7978845608028654f * (v + 0.044715f * v * v * v);
    return 0.5f * v * (1.0f + tanh_ap(u));
}

// ---------------- sort-by-dst machinery ----------------
__global__ void k_zero() {
    int i = blockIdx.x * blockDim.x + threadIdx.x;
    if (i < NN) g_cnt[i] = 0;
}

__global__ void k_hist(const int* __restrict__ dst) {
    int e = blockIdx.x * blockDim.x + threadIdx.x;
    if (e < EE) atomicAdd(&g_cnt[dst[e]], 1);
}

__global__ void k_scan() {
    __shared__ int part[1024];
    int t = threadIdx.x;
    const int CH = (NN + 1023) / 1024;  // 20
    int base = t * CH;
    int s = 0;
    for (int i = 0; i < CH; i++) {
        int idx = base + i;
        if (idx < NN) s += g_cnt[idx];
    }
    part[t] = s;
    __syncthreads();
    for (int off = 1; off < 1024; off <<= 1) {
        int v = 0;
        if (t >= off) v = part[t - off];
        __syncthreads();
        part[t] += v;
        __syncthreads();
    }
    int run = (t == 0) ? 0 : part[t - 1];
    for (int i = 0; i < CH; i++) {
        int idx = base + i;
        if (idx < NN) {
            g_row[idx] = run;
            g_cur[idx] = run;
            run += g_cnt[idx];
        }
    }
    if (t == 1023) g_row[NN] = part[1023];
}

__global__ void k_place(const int* __restrict__ dst) {
    int e = blockIdx.x * blockDim.x + threadIdx.x;
    if (e < EE) {
        int p = atomicAdd(&g_cur[dst[e]], 1);
        g_ord[p] = e;
    }
}

// ---------------- K1: first equivariant Linear ----------------
__global__ void k_lin1(const float* __restrict__ nsc, const float* __restrict__ nvec,
                       const float* __restrict__ W1sf, const float* __restrict__ W1ssw,
                       const float* __restrict__ W1vf, const float* __restrict__ W1vs) {
    __shared__ float wsf[1024], wss[1024], wvf[1024], wvs[1024];
    int t = threadIdx.x;
    for (int i = t; i < 1024; i += 256) {
        wsf[i] = W1sf[i];
        wss[i] = W1ssw[i];
        wvf[i] = W1vf[i];
        wvs[i] = W1vs[i];
    }
    __syncthreads();
    int warp = t >> 5, lane = t & 31;
    int n = blockIdx.x * 8 + warp;

    float s_l  = nsc[n * 32 + lane];
    int   b3l  = (n * 32 + lane) * 3;
    float vx_l = nvec[b3l + 0];
    float vy_l = nvec[b3l + 1];
    float vz_l = nvec[b3l + 2];

    float fs = 0.f, ss = 0.f;
    float fvx = 0.f, fvy = 0.f, fvz = 0.f;
    float svx = 0.f, svy = 0.f, svz = 0.f;
#pragma unroll
    for (int u = 0; u < 32; u++) {
        float s  = __shfl_sync(0xffffffffu, s_l, u);
        float vx = __shfl_sync(0xffffffffu, vx_l, u);
        float vy = __shfl_sync(0xffffffffu, vy_l, u);
        float vz = __shfl_sync(0xffffffffu, vz_l, u);
        float a = wsf[u * 32 + lane];
        float b = wss[u * 32 + lane];
        float c = wvf[u * 32 + lane];
        float d = wvs[u * 32 + lane];
        fs += s * a;
        ss += s * b;
        fvx += vx * c; fvy += vy * c; fvz += vz * c;
        svx += vx * d; svy += vy * d; svz += vz * d;
    }
    const float inv = 0.17677669529663687f;  // 1/sqrt(32)
    g_fs[n * 32 + lane] = fs * inv;
    g_ss[n * 32 + lane] = ss * inv;
    int b3 = (n * 32 + lane) * 3;
    g_fv[b3 + 0] = fvx * inv; g_fv[b3 + 1] = fvy * inv; g_fv[b3 + 2] = fvz * inv;
    g_sv[b3 + 0] = svx * inv; g_sv[b3 + 1] = svy * inv; g_sv[b3 + 2] = svz * inv;
}

// ---------------- K2a: radial MLP, 2 edges/thread via packed f32x2 ----------------
// smem holds weights duplicated into both halves of a b64 pair so the inner
// loops are pure LDS.128 + fma.rn.f32x2 (SASS FFMA2, double fp32 rate).
__global__ void __launch_bounds__(256) k_mlp(const float* __restrict__ esa,
                                             const float* __restrict__ Wmlp0,
                                             const float* __restrict__ Wmlp1,
                                             const float* __restrict__ Wi0,
                                             const float* __restrict__ Wi1,
                                             const float* __restrict__ Wi2,
                                             const float* __restrict__ Wi3) {
    extern __shared__ ull smp[];
    ull* wm0T = smp;                 // [64][16]  packed (transposed Wmlp0)
    ull* wm1  = smp + 1024;          // [64][64]  packed row-major [k][j]
    ull* wi   = smp + 1024 + 4096;   // [64][128] packed [k][m*32+u]
    int t = threadIdx.x;
    for (int i = t; i < 1024; i += 256) {
        int k = i & 15, j = i >> 4;
        float w = Wmlp0[k * 64 + j];
        wm0T[j * 16 + k] = pk2(w, w);
    }
    for (int i = t; i < 4096; i += 256) {
        float w = Wmlp1[i];
        wm1[i] = pk2(w, w);
    }
    for (int i = t; i < 2048; i += 256) {
        int k = i >> 5, u = i & 31;
        float a = Wi0[i], b = Wi1[i], c = Wi2[i], d = Wi3[i];
        wi[k * 128 + u]      = pk2(a, a);
        wi[k * 128 + 32 + u] = pk2(b, b);
        wi[k * 128 + 64 + u] = pk2(c, c);
        wi[k * 128 + 96 + u] = pk2(d, d);
    }
    __syncthreads();

    int e0 = blockIdx.x * 512 + t;      // edges e0 (lo lane) and e0+256 (hi lane)
    int e1 = e0 + 256;

    ull x[16];
    {
        const float4* p0 = (const float4*)(esa + (size_t)e0 * 16);
        const float4* p1 = (const float4*)(esa + (size_t)e1 * 16);
#pragma unroll
        for (int q = 0; q < 4; q++) {
            float4 a = p0[q], b = p1[q];
            x[q * 4 + 0] = pk2(a.x, b.x);
            x[q * 4 + 1] = pk2(a.y, b.y);
            x[q * 4 + 2] = pk2(a.z, b.z);
            x[q * 4 + 3] = pk2(a.w, b.w);
        }
    }

    const ull Q2 = pk2(0.25f, 0.25f);    // 1/sqrt(16)
    const ull E2 = pk2(0.125f, 0.125f);  // 1/sqrt(64)

    ull h[64];
#pragma unroll
    for (int j = 0; j < 64; j++) h[j] = 0ull;

    // fused stage1 + stage2
    for (int k2 = 0; k2 < 64; k2++) {
        ull t0 = 0ull;
        const ulonglong2* wc = (const ulonglong2*)(wm0T + k2 * 16);
#pragma unroll
        for (int kq = 0; kq < 8; kq++) {
            ulonglong2 w = wc[kq];
            t0 = fma2(x[kq * 2 + 0], w.x, t0);
            t0 = fma2(x[kq * 2 + 1], w.y, t0);
        }
        t0 = gelu2(mul2(t0, Q2));
        const ulonglong2* wr = (const ulonglong2*)(wm1 + k2 * 64);
#pragma unroll
        for (int j2 = 0; j2 < 32; j2++) {
            ulonglong2 w = wr[j2];
            h[j2 * 2 + 0] = fma2(t0, w.x, h[j2 * 2 + 0]);
            h[j2 * 2 + 1] = fma2(t0, w.y, h[j2 * 2 + 1]);
        }
    }
#pragma unroll
    for (int j = 0; j < 64; j++) h[j] = gelu2(mul2(h[j], E2));

    // stage3: 128 outputs in chunks of 8
    float* wout0 = g_w + (size_t)e0 * 128;
    float* wout1 = g_w + (size_t)e1 * 128;
    for (int g = 0; g < 16; g++) {
        ull acc[8];
#pragma unroll
        for (int q = 0; q < 8; q++) acc[q] = 0ull;
        const ull* wb = wi + g * 8;
#pragma unroll
        for (int k = 0; k < 64; k++) {
            const ulonglong2* wk = (const ulonglong2*)(wb + k * 128);
            ulonglong2 wa = wk[0], wb2 = wk[1], wc = wk[2], wd = wk[3];
            ull hk = h[k];
            acc[0] = fma2(hk, wa.x, acc[0]);
            acc[1] = fma2(hk, wa.y, acc[1]);
            acc[2] = fma2(hk, wb2.x, acc[2]);
            acc[3] = fma2(hk, wb2.y, acc[3]);
            acc[4] = fma2(hk, wc.x, acc[4]);
            acc[5] = fma2(hk, wc.y, acc[5]);
            acc[6] = fma2(hk, wd.x, acc[6]);
            acc[7] = fma2(hk, wd.y, acc[7]);
        }
        float lo[8], hi[8];
#pragma unroll
        for (int q = 0; q < 8; q++) {
            acc[q] = mul2(acc[q], E2);  // /sqrt(64)
            upk2(acc[q], lo[q], hi[q]);
        }
        *(float4*)(wout0 + g * 8)     = make_float4(lo[0], lo[1], lo[2], lo[3]);
        *(float4*)(wout0 + g * 8 + 4) = make_float4(lo[4], lo[5], lo[6], lo[7]);
        *(float4*)(wout1 + g * 8)     = make_float4(hi[0], hi[1], hi[2], hi[3]);
        *(float4*)(wout1 + g * 8 + 4) = make_float4(hi[4], hi[5], hi[6], hi[7]);
    }
}

// ---------------- K2b: gather + tensor product + segment reduce ----------------
__global__ void k_gather(const float* __restrict__ eas, const float* __restrict__ eav,
                         const int* __restrict__ src) {
    int t = threadIdx.x;
    int n = (blockIdx.x * blockDim.x + t) >> 5;
    int lane = t & 31;
    int beg = g_row[n], end = g_row[n + 1];

    float a0 = 0.f, a3 = 0.f;
    float a1x = 0.f, a1y = 0.f, a1z = 0.f;
    float a2x = 0.f, a2y = 0.f, a2z = 0.f;

    for (int base = beg; base < end; base += 32) {
        int cnt = min(32, end - base);
        int idx = 0, s = 0;
        float vx = 0.f, vy = 0.f, vz = 0.f, ea = 0.f;
        if (lane < cnt) {
            idx = g_ord[base + lane];
            s = src[idx];
            vx = eav[idx * 3 + 0];
            vy = eav[idx * 3 + 1];
            vz = eav[idx * 3 + 2];
            ea = eas[idx];
        }
        for (int i = 0; i < cnt; i++) {
            int ide = __shfl_sync(0xffffffffu, idx, i);
            int se  = __shfl_sync(0xffffffffu, s, i);
            float evx = __shfl_sync(0xffffffffu, vx, i);
            float evy = __shfl_sync(0xffffffffu, vy, i);
            float evz = __shfl_sync(0xffffffffu, vz, i);
            float eae = __shfl_sync(0xffffffffu, ea, i);

            const float* wp = g_w + (size_t)ide * 128;
            float w0 = wp[lane];
            float w1 = wp[32 + lane];
            float w2 = wp[64 + lane];
            float w3 = wp[96 + lane];
            float es = g_fs[se * 32 + lane];
            int b3 = (se * 32 + lane) * 3;
            float fx = g_fv[b3 + 0];
            float fy = g_fv[b3 + 1];
            float fz = g_fv[b3 + 2];

            float dot = fx * evx + fy * evy + fz * evz;
            a0 += w0 * es * eae;
            a3 += w3 * dot;
            float w1es = w1 * es;
            a1x += w1es * evx; a1y += w1es * evy; a1z += w1es * evz;
            float w2ea = w2 * eae;
            a2x += w2ea * fx; a2y += w2ea * fy; a2z += w2ea * fz;
        }
    }

    const float inv_nb = 0.17677669529663687f;  // 1/sqrt(32)
    const float inv_s3 = 0.5773502691896258f;   // 1/sqrt(3)
    g_ns[n * 64 + lane]      = a0 * inv_nb;
    g_ns[n * 64 + 32 + lane] = a3 * inv_s3 * inv_nb;
    int ba = n * 192 + lane * 3;
    g_nv[ba + 0] = a1x * inv_nb; g_nv[ba + 1] = a1y * inv_nb; g_nv[ba + 2] = a1z * inv_nb;
    int bb = n * 192 + (32 + lane) * 3;
    g_nv[bb + 0] = a2x * inv_nb; g_nv[bb + 1] = a2y * inv_nb; g_nv[bb + 2] = a2z * inv_nb;
}

// ---------------- K3: second Linear + self-connection mix ----------------
__global__ void k_lin2(const float* __restrict__ W2s, const float* __restrict__ W2v,
                       float* __restrict__ out) {
    __shared__ float w2s[2048], w2v[2048];
    int t = threadIdx.x;
    for (int i = t; i < 2048; i += 256) {
        w2s[i] = W2s[i];
        w2v[i] = W2v[i];
    }
    __syncthreads();
    int warp = t >> 5, lane = t & 31;
    int n = blockIdx.x * 8 + warp;

    float nsa = g_ns[n * 64 + lane];
    float nsb = g_ns[n * 64 + 32 + lane];
    int ba = n * 192 + lane * 3;
    int bb = n * 192 + (32 + lane) * 3;
    float vax = g_nv[ba + 0], vay = g_nv[ba + 1], vaz = g_nv[ba + 2];
    float vbx = g_nv[bb + 0], vby = g_nv[bb + 1], vbz = g_nv[bb + 2];

    float cs = 0.f, cvx = 0.f, cvy = 0.f, cvz = 0.f;
#pragma unroll
    for (int j = 0; j < 32; j++) {
        float sj = __shfl_sync(0xffffffffu, nsa, j);
        float xj = __shfl_sync(0xffffffffu, vax, j);
        float yj = __shfl_sync(0xffffffffu, vay, j);
        float zj = __shfl_sync(0xffffffffu, vaz, j);
        float ws = w2s[j * 32 + lane];
        float wv = w2v[j * 32 + lane];
        cs += sj * ws;
        cvx += xj * wv; cvy += yj * wv; cvz += zj * wv;
    }
#pragma unroll
    for (int j = 0; j < 32; j++) {
        float sj = __shfl_sync(0xffffffffu, nsb, j);
        float xj = __shfl_sync(0xffffffffu, vbx, j);
        float yj = __shfl_sync(0xffffffffu, vby, j);
        float zj = __shfl_sync(0xffffffffu, vbz, j);
        float ws = w2s[(32 + j) * 32 + lane];
        float wv = w2v[(32 + j) * 32 + lane];
        cs += sj * ws;
        cvx += xj * wv; cvy += yj * wv; cvz += zj * wv;
    }
    const float inv_mid = 0.125f;                 // 1/sqrt(64)
    const float cc = 0.9238795325112867f;         // cos(pi/8)
    const float sc = 0.3826834323650898f;         // sin(pi/8)
    float ssv = g_ss[n * 32 + lane];
    out[n * 32 + lane] = cc * ssv + sc * cs * inv_mid;

    int b3 = (n * 32 + lane) * 3;
    float* ov = out + NN * 32;
    ov[b3 + 0] = cc * g_sv[b3 + 0] + sc * cvx * inv_mid;
    ov[b3 + 1] = cc * g_sv[b3 + 1] + sc * cvy * inv_mid;
    ov[b3 + 2] = cc * g_sv[b3 + 2] + sc * cvz * inv_mid;
}

// ---------------- launch ----------------
extern "C" void kernel_launch(void* const* d_in, const int* in_sizes, int n_in,
                              void* d_out, int out_size) {
    const float* node_scalars = (const float*)d_in[0];
    const float* node_vectors = (const float*)d_in[1];
    const float* edge_attr_s  = (const float*)d_in[2];
    const float* edge_attr_v  = (const float*)d_in[3];
    const float* edge_scalar  = (const float*)d_in[4];
    const int*   edge_src     = (const int*)d_in[5];
    const int*   edge_dst     = (const int*)d_in[6];
    const float* W1s_feat     = (const float*)d_in[7];
    const float* W1s_self     = (const float*)d_in[8];
    const float* W1v_feat     = (const float*)d_in[9];
    const float* W1v_self     = (const float*)d_in[10];
    const float* Wmlp0        = (const float*)d_in[11];
    const float* Wmlp1        = (const float*)d_in[12];
    const float* Wi0          = (const float*)d_in[13];
    const float* Wi1          = (const float*)d_in[14];
    const float* Wi2          = (const float*)d_in[15];
    const float* Wi3          = (const float*)d_in[16];
    const float* W2s          = (const float*)d_in[17];
    const float* W2v          = (const float*)d_in[18];
    float* out = (float*)d_out;

    static bool attr_set = false;
    if (!attr_set) {
        cudaFuncSetAttribute(k_mlp, cudaFuncAttributeMaxDynamicSharedMemorySize, 13312 * 8);
        attr_set = true;
    }

    // sort edges by destination
    k_zero<<<(NN + 255) / 256, 256>>>();
    k_hist<<<EE / 256, 256>>>(edge_dst);
    k_scan<<<1, 1024>>>();
    k_place<<<EE / 256, 256>>>(edge_dst);

    // node linear 1
    k_lin1<<<NN / 8, 256>>>(node_scalars, node_vectors, W1s_feat, W1s_self, W1v_feat, W1v_self);

    // per-edge radial MLP (2 edges per thread, packed f32x2)
    k_mlp<<<EE / 512, 256, 13312 * 8>>>(edge_scalar, Wmlp0, Wmlp1, Wi0, Wi1, Wi2, Wi3);

    // gather + tensor product + segment sum
    k_gather<<<(NN * 32) / 256, 256>>>(edge_attr_s, edge_attr_v, edge_src);

    // node linear 2 + mix
    k_lin2<<<NN / 8, 256>>>(W2s, W2v, out);
}